// round 16
// baseline (speedup 1.0000x reference)
#include <cuda_runtime.h>
#include <math.h>

#define BATCH 4
#define NPTS  4096
#define KNN   20
#define CATC  512
#define EPSBN 1e-5f
#define NEGINF -3.402823466e38f
#define CAP    4096
#define SBUF   192

typedef unsigned long long u64;
typedef unsigned int u32;

// ---------------- scratch (static device globals; no allocations) ----------
__device__ float g_candV[(size_t)BATCH * NPTS * CAP];   // 256 MB
__device__ int   g_candJ[(size_t)BATCH * NPTS * CAP];   // 256 MB
__device__ int   g_cnt  [BATCH * NPTS];
__device__ float g_thr  [BATCH * NPTS];
__device__ int   g_idx [(size_t)BATCH * NPTS * KNN];
__device__ float g_xx  [BATCH * NPTS];
__device__ float g_cat [(size_t)BATCH * NPTS * CATC];   // 32 MB
__device__ float g_UV  [(size_t)BATCH * NPTS * 512];    // 32 MB
__device__ float g_Wuv [512 * 256];
__device__ float g_Zp  [BATCH * 512 * 32];

// ===================== packed f32x2 helpers =================================
__device__ __forceinline__ void fma2(u64& d, u64 a, u64 b) {
    asm("fma.rn.f32x2 %0, %1, %2, %0;" : "+l"(d) : "l"(a), "l"(b));
}
__device__ __forceinline__ u64 dup2(float a) {
    u64 d;
    asm("mov.b64 %0, {%1, %1};" : "=l"(d) : "f"(a));
    return d;
}
__device__ __forceinline__ void unpack2(u64 p, float& lo, float& hi) {
    asm("mov.b64 {%0, %1}, %2;" : "=f"(lo), "=f"(hi) : "l"(p));
}

// monotonic float->u32 order map
__device__ __forceinline__ u32 mapf(float f) {
    u32 u = __float_as_uint(f);
    return u ^ ((u32)(((int)u) >> 31) | 0x80000000u);
}

// ---------------- row squared norms ----------------------------------------
__global__ void xx_kernel(const float* __restrict__ X, int ldx, int C,
                          float* __restrict__ xx) {
    int r = blockIdx.x * blockDim.x + threadIdx.x;
    if (r >= BATCH * NPTS) return;
    const float* row = X + (size_t)r * ldx;
    float s = 0.f;
    if (C == 3) {
        float a = row[0], b = row[1], c = row[2];
        s = a * a + b * b + c * c;
    } else {
        for (int c = 0; c < C; c += 4) {
            float4 v = *reinterpret_cast<const float4*>(row + c);
            s += v.x * v.x + v.y * v.y + v.z * v.z + v.w * v.w;
        }
    }
    xx[r] = s;
}

// ===================== fused Gram + running-top2 candidate emit =============
// 64-row i-tile per block (4x8 thread-tile, ~half register state -> natural
// occupancy 2). value = 2*inner(i,j) - ||xj||^2. Monotone safe threshold,
// smem counters. Dynamic smem: As[C][68] | Bs[C][132] | scnt[64]
template <int C, bool COORD>
__global__ __launch_bounds__(256)
void gramcand_kernel(const float* __restrict__ X, int ldx,
                     const float* __restrict__ xx,
                     float* __restrict__ candV, int* __restrict__ candJ,
                     int* __restrict__ cnt, float* __restrict__ thr) {
    extern __shared__ float smem[];
    float* As = smem;                   // [C][68]
    float* Bs = smem + C * 68;          // [C][132]
    int* scnt = (int*)(Bs + C * 132);   // [64]
#define AS_(k, r) As[(k) * 68 + (r)]
#define BS_(k, r) Bs[(k) * 132 + (r)]

    int b = blockIdx.z;
    const float* Xb  = X  + (size_t)b * NPTS * ldx;
    const float* xxb = xx + (size_t)b * NPTS;
    int i0 = blockIdx.x * 64;
    int tid = threadIdx.x, tx = tid & 15, ty = tid >> 4;
    int lr4 = tid >> 2, lq = tid & 3;   // A loads: 64 rows x 4 col-quads
    int lr = tid >> 1, lh = tid & 1;    // B loads: 128 rows x 2 col-halves
    int gi0 = b * NPTS + i0;

    // ---- load A-tile (64 rows x C) ----
    if (COORD) {
        if (tid < 64) {
            const float* xr = &Xb[(size_t)(i0 + tid) * 3];
            AS_(0, tid) = xr[0]; AS_(1, tid) = xr[1]; AS_(2, tid) = xr[2];
#pragma unroll
            for (int k = 3; k < C; k++) AS_(k, tid) = 0.f;
        }
    } else {
#pragma unroll
        for (int m = 0; m < C / 16; m++) {
            float4 v = *reinterpret_cast<const float4*>(
                &Xb[(size_t)(i0 + lr4) * ldx + m * 16 + lq * 4]);
            AS_(m * 16 + lq * 4 + 0, lr4) = v.x;
            AS_(m * 16 + lq * 4 + 1, lr4) = v.y;
            AS_(m * 16 + lq * 4 + 2, lr4) = v.z;
            AS_(m * 16 + lq * 4 + 3, lr4) = v.w;
        }
    }
    if (tid < 64) scnt[tid] = 0;

    // running per-lane top-2 per owned row (4 rows/thread-row-group)
    float l1[4], l2[4];
#pragma unroll
    for (int rr = 0; rr < 4; rr++) { l1[rr] = NEGINF; l2[rr] = NEGINF; }

    __syncthreads();

    for (int jt = 0; jt < 32; jt++) {
        int j0 = jt * 128;
        // ---- load B-tile (128 rows x C) ----
        if (COORD) {
            if (tid < 128) {
                const float* xr = &Xb[(size_t)(j0 + tid) * 3];
                BS_(0, tid) = xr[0]; BS_(1, tid) = xr[1]; BS_(2, tid) = xr[2];
#pragma unroll
                for (int k = 3; k < C; k++) BS_(k, tid) = 0.f;
            }
        } else {
#pragma unroll
            for (int m = 0; m < C / 8; m++) {
                float4 v = *reinterpret_cast<const float4*>(
                    &Xb[(size_t)(j0 + lr) * ldx + m * 8 + lh * 4]);
                BS_(m * 8 + lh * 4 + 0, lr) = v.x;
                BS_(m * 8 + lh * 4 + 1, lr) = v.y;
                BS_(m * 8 + lh * 4 + 2, lr) = v.z;
                BS_(m * 8 + lh * 4 + 3, lr) = v.w;
            }
        }
        __syncthreads();

        // ---- compute 64x128 tile, no syncs inside ----
        u64 acc[4][4];
#pragma unroll
        for (int ii = 0; ii < 4; ii++)
#pragma unroll
            for (int jp = 0; jp < 4; jp++) acc[ii][jp] = 0ULL;

        for (int kk0 = 0; kk0 < C; kk0 += 8) {
#pragma unroll
            for (int k2 = 0; k2 < 8; k2++) {
                int kk = kk0 + k2;
                float4 a0 = *reinterpret_cast<const float4*>(&AS_(kk, ty * 4));
                ulonglong2 b0 = *reinterpret_cast<const ulonglong2*>(&BS_(kk, tx * 4));
                ulonglong2 b1 = *reinterpret_cast<const ulonglong2*>(&BS_(kk, 64 + tx * 4));
                u64 bq[4] = {b0.x, b0.y, b1.x, b1.y};
                float a[4] = {a0.x, a0.y, a0.z, a0.w};
#pragma unroll
                for (int ii = 0; ii < 4; ii++) {
                    u64 ad = dup2(a[ii]);
#pragma unroll
                    for (int jp = 0; jp < 4; jp++) fma2(acc[ii][jp], ad, bq[jp]);
                }
            }
        }

        // ---- epilogue: running top-2 threshold + candidate emit (smem cnt) --
        float4 xjA = *reinterpret_cast<const float4*>(&xxb[j0 + tx * 4]);
        float4 xjB = *reinterpret_cast<const float4*>(&xxb[j0 + 64 + tx * 4]);
        float xj[8] = {xjA.x, xjA.y, xjA.z, xjA.w, xjB.x, xjB.y, xjB.z, xjB.w};

#pragma unroll
        for (int rr = 0; rr < 4; rr++) {
            float c[8];
#pragma unroll
            for (int jp = 0; jp < 4; jp++) unpack2(acc[rr][jp], c[jp * 2], c[jp * 2 + 1]);
            float dv[8];
#pragma unroll
            for (int jj = 0; jj < 8; jj++) dv[jj] = 2.f * c[jj] - xj[jj];

            // update running lane top-2; track current-tile lane max
            float m1 = l1[rr], m2 = l2[rr];
            float cmax = dv[0];
#pragma unroll
            for (int jj = 0; jj < 8; jj++) {
                float v = dv[jj];
                cmax = fmaxf(cmax, v);
                float n1 = fmaxf(m1, v);
                m2 = fmaxf(m2, fminf(m1, v));
                m1 = n1;
            }
            l1[rr] = m1; l2[rr] = m2;

            // t = min over the 16 lanes owning this row (xor<16 stays in half)
            float t = m2;
#pragma unroll
            for (int off = 1; off < 16; off <<= 1)
                t = fminf(t, __shfl_xor_sync(0xffffffffu, t, off));

            int rloc = ty * 4 + rr;
            size_t base = (size_t)(gi0 + rloc) * CAP;
            if (cmax >= t) {
#pragma unroll
                for (int jj = 0; jj < 8; jj++) {
                    if (dv[jj] >= t) {
                        int pos = atomicAdd(&scnt[rloc], 1);  // pos < NPTS = CAP always
                        int j = (jj < 4) ? (j0 + tx * 4 + jj)
                                         : (j0 + 64 + tx * 4 + jj - 4);
                        candV[base + pos] = dv[jj];
                        candJ[base + pos] = j;
                    }
                }
            }
        }
        __syncthreads();
    }

    // ---- export counts + final per-row safe threshold ----
    if (tid < 64) cnt[gi0 + tid] = scnt[tid];
#pragma unroll
    for (int rr = 0; rr < 4; rr++) {
        float t = l2[rr];
#pragma unroll
        for (int off = 1; off < 16; off <<= 1)
            t = fminf(t, __shfl_xor_sync(0xffffffffu, t, off));
        if (tx == 0) thr[gi0 + ty * 4 + rr] = t;
    }
#undef AS_
#undef BS_
}

// ---------------- merge candidates -> exact top-K (single-pass) ------------
__global__ __launch_bounds__(256)
void merge3_kernel(const float* __restrict__ candV, const int* __restrict__ candJ,
                   const int* __restrict__ cnt, const float* __restrict__ thr,
                   int* __restrict__ idx) {
    __shared__ u64 surv[8][SBUF];
    int warp = threadIdx.x >> 5, lane = threadIdx.x & 31;
    int row = blockIdx.x * 8 + warp;
    int n = cnt[row];
    float T = thr[row];
    const float* cv = candV + (size_t)row * CAP;
    const int*   cj = candJ + (size_t)row * CAP;

    int sc = 0;
    for (int base = 0; base < n; base += 32) {
        int t = base + lane;
        float v = (t < n) ? cv[t] : NEGINF;
        bool keep = (t < n) && (v >= T);
        unsigned mk = __ballot_sync(0xffffffffu, keep);
        if (keep) {
            int pos = sc + __popc(mk & ((1u << lane) - 1u));
            if (pos < SBUF)
                surv[warp][pos] = ((u64)mapf(v) << 32) | (u32)(4095 - cj[t]);
        }
        sc += __popc(mk);
    }
    __syncwarp();

    int* outp = idx + (size_t)row * KNN;
    if (sc <= SBUF) {
        for (int k = 0; k < KNN; k++) {
            u64 best = 0ULL; int bpos = -1;
            for (int t = lane; t < sc; t += 32) {
                u64 kv = surv[warp][t];
                if (kv > best) { best = kv; bpos = t; }
            }
#pragma unroll
            for (int off = 16; off > 0; off >>= 1) {
                u64 ov = __shfl_xor_sync(0xffffffffu, best, off);
                int op = __shfl_xor_sync(0xffffffffu, bpos, off);
                if (ov > best) { best = ov; bpos = op; }
            }
            if (lane == 0) {
                outp[k] = 4095 - (int)(best & 0xFFFu);
                surv[warp][bpos] = 0ULL;
            }
            __syncwarp();
        }
    } else {
        u64 last = 0xFFFFFFFFFFFFFFFFULL;
        for (int k = 0; k < KNN; k++) {
            u64 best = 0ULL;
            for (int t = lane; t < n; t += 32) {
                u64 kv = ((u64)mapf(cv[t]) << 32) | (u32)(4095 - cj[t]);
                if (kv < last && kv > best) best = kv;
            }
#pragma unroll
            for (int off = 16; off > 0; off >>= 1) {
                u64 ov = __shfl_xor_sync(0xffffffffu, best, off);
                if (ov > best) best = ov;
            }
            if (lane == 0) outp[k] = 4095 - (int)(best & 0xFFFu);
            last = best;
        }
    }
}

// ---------------- generic NT GEMM: Out[i,j] = A[i,:]·B[j,:] -----------------
#define GPADF 132
__global__ __launch_bounds__(256, 2)
void gemm128_kernel(const float* __restrict__ A, int lda,
                    const float* __restrict__ B, int ldb, int nB,
                    int K, float* __restrict__ Out, int ldo) {
    __shared__ float As[8][GPADF];
    __shared__ float Bs[8][GPADF];
    int i0 = blockIdx.x * 128, j0 = blockIdx.y * 128;
    int tid = threadIdx.x, tx = tid & 15, ty = tid >> 4;
    int lr = tid >> 1, lh = tid & 1;

    u64 acc[8][4];
#pragma unroll
    for (int ii = 0; ii < 8; ii++)
#pragma unroll
        for (int jp = 0; jp < 4; jp++) acc[ii][jp] = 0ULL;

    int nt = K >> 3;
    float4 pa = *reinterpret_cast<const float4*>(&A[(size_t)(i0 + lr) * lda + lh * 4]);
    float4 pb = (j0 + lr < nB)
              ? *reinterpret_cast<const float4*>(&B[(size_t)(j0 + lr) * ldb + lh * 4])
              : make_float4(0.f, 0.f, 0.f, 0.f);

    for (int kt = 0; kt < nt; kt++) {
        As[lh * 4 + 0][lr] = pa.x; As[lh * 4 + 1][lr] = pa.y;
        As[lh * 4 + 2][lr] = pa.z; As[lh * 4 + 3][lr] = pa.w;
        Bs[lh * 4 + 0][lr] = pb.x; Bs[lh * 4 + 1][lr] = pb.y;
        Bs[lh * 4 + 2][lr] = pb.z; Bs[lh * 4 + 3][lr] = pb.w;
        __syncthreads();
        if (kt + 1 < nt) {
            int k0 = (kt + 1) * 8 + lh * 4;
            pa = *reinterpret_cast<const float4*>(&A[(size_t)(i0 + lr) * lda + k0]);
            pb = (j0 + lr < nB)
               ? *reinterpret_cast<const float4*>(&B[(size_t)(j0 + lr) * ldb + k0])
               : make_float4(0.f, 0.f, 0.f, 0.f);
        }
#pragma unroll
        for (int kk = 0; kk < 8; kk++) {
            float4 a0 = *reinterpret_cast<const float4*>(&As[kk][ty * 8]);
            float4 a1 = *reinterpret_cast<const float4*>(&As[kk][ty * 8 + 4]);
            ulonglong2 b0 = *reinterpret_cast<const ulonglong2*>(&Bs[kk][tx * 8]);
            ulonglong2 b1 = *reinterpret_cast<const ulonglong2*>(&Bs[kk][tx * 8 + 4]);
            u64 bq[4] = {b0.x, b0.y, b1.x, b1.y};
            float a[8] = {a0.x, a0.y, a0.z, a0.w, a1.x, a1.y, a1.z, a1.w};
#pragma unroll
            for (int ii = 0; ii < 8; ii++) {
                u64 ad = dup2(a[ii]);
#pragma unroll
                for (int jp = 0; jp < 4; jp++) fma2(acc[ii][jp], ad, bq[jp]);
            }
        }
        __syncthreads();
    }

    int j = j0 + tx * 8;
    if (j < nB) {
#pragma unroll
        for (int ii = 0; ii < 8; ii++) {
            int i = i0 + ty * 8 + ii;
            float c[8];
#pragma unroll
            for (int jp = 0; jp < 4; jp++) unpack2(acc[ii][jp], c[jp * 2], c[jp * 2 + 1]);
            float* dst = &Out[(size_t)i * ldo + j];
            *reinterpret_cast<float4*>(dst)     = make_float4(c[0], c[1], c[2], c[3]);
            *reinterpret_cast<float4*>(dst + 4) = make_float4(c[4], c[5], c[6], c[7]);
        }
    }
}

// ---------------- layer 4: GEMM + max-over-N epilogue -----------------------
__global__ __launch_bounds__(256, 2)
void conv4max128_kernel(const float* __restrict__ cat, const float* __restrict__ W4,
                        float* __restrict__ Zp) {
    __shared__ float As[8][GPADF];
    __shared__ float Bs[8][GPADF];
    __shared__ float red[128][17];
    int b = blockIdx.z, seg = blockIdx.y;
    int o0 = blockIdx.x * 128, n0 = seg * 128;
    const float* catb = cat + (size_t)b * NPTS * CATC;
    int tid = threadIdx.x, tx = tid & 15, ty = tid >> 4;
    int lr = tid >> 1, lh = tid & 1;

    u64 acc[8][4];
#pragma unroll
    for (int ii = 0; ii < 8; ii++)
#pragma unroll
        for (int jp = 0; jp < 4; jp++) acc[ii][jp] = 0ULL;

    float4 pa = *reinterpret_cast<const float4*>(&W4  [(size_t)(o0 + lr) * CATC + lh * 4]);
    float4 pb = *reinterpret_cast<const float4*>(&catb[(size_t)(n0 + lr) * CATC + lh * 4]);

    for (int kt = 0; kt < 64; kt++) {
        As[lh * 4 + 0][lr] = pa.x; As[lh * 4 + 1][lr] = pa.y;
        As[lh * 4 + 2][lr] = pa.z; As[lh * 4 + 3][lr] = pa.w;
        Bs[lh * 4 + 0][lr] = pb.x; Bs[lh * 4 + 1][lr] = pb.y;
        Bs[lh * 4 + 2][lr] = pb.z; Bs[lh * 4 + 3][lr] = pb.w;
        __syncthreads();
        if (kt + 1 < 64) {
            int k0 = (kt + 1) * 8 + lh * 4;
            pa = *reinterpret_cast<const float4*>(&W4  [(size_t)(o0 + lr) * CATC + k0]);
            pb = *reinterpret_cast<const float4*>(&catb[(size_t)(n0 + lr) * CATC + k0]);
        }
#pragma unroll
        for (int kk = 0; kk < 8; kk++) {
            float4 a0 = *reinterpret_cast<const float4*>(&As[kk][ty * 8]);
            float4 a1 = *reinterpret_cast<const float4*>(&As[kk][ty * 8 + 4]);
            ulonglong2 b0 = *reinterpret_cast<const ulonglong2*>(&Bs[kk][tx * 8]);
            ulonglong2 b1 = *reinterpret_cast<const ulonglong2*>(&Bs[kk][tx * 8 + 4]);
            u64 bq[4] = {b0.x, b0.y, b1.x, b1.y};
            float a[8] = {a0.x, a0.y, a0.z, a0.w, a1.x, a1.y, a1.z, a1.w};
#pragma unroll
            for (int ii = 0; ii < 8; ii++) {
                u64 ad = dup2(a[ii]);
#pragma unroll
                for (int jp = 0; jp < 4; jp++) fma2(acc[ii][jp], ad, bq[jp]);
            }
        }
        __syncthreads();
    }

#pragma unroll
    for (int ii = 0; ii < 8; ii++) {
        float c[8];
#pragma unroll
        for (int jp = 0; jp < 4; jp++) unpack2(acc[ii][jp], c[jp * 2], c[jp * 2 + 1]);
        float m = c[0];
#pragma unroll
        for (int q = 1; q < 8; q++) m = fmaxf(m, c[q]);
        red[ty * 8 + ii][tx] = m;
    }
    __syncthreads();
    if (tid < 128) {
        float m = red[tid][0];
#pragma unroll
        for (int t = 1; t < 16; t++) m = fmaxf(m, red[tid][t]);
        Zp[((size_t)b * 512 + o0 + tid) * 32 + seg] = m;
    }
}

// ---------------- block 0 conv (coords, 9-ch edge feature with cross) ------
__global__ void edge0_kernel(const float* __restrict__ x, const int* __restrict__ idx,
                             const float* __restrict__ W,  const float* __restrict__ gg,
                             const float* __restrict__ bb, const float* __restrict__ mm,
                             const float* __restrict__ vv, float* __restrict__ cat) {
    int p = blockIdx.x;
    int b = p / NPTS;
    __shared__ float nb[KNN][3];
    __shared__ float Ws[64 * 9];
    __shared__ float cc[3];
    int tid = threadIdx.x;  // 64 threads
    if (tid < 3) cc[tid] = x[(size_t)p * 3 + tid];
    if (tid < KNN) {
        int j = idx[(size_t)p * KNN + tid];
        const float* xr = x + ((size_t)b * NPTS + j) * 3;
        nb[tid][0] = xr[0]; nb[tid][1] = xr[1]; nb[tid][2] = xr[2];
    }
    for (int t = tid; t < 576; t += 64) Ws[t] = W[t];
    __syncthreads();

    int o = tid;
    const float* w = &Ws[o * 9];
    float c0 = cc[0], c1 = cc[1], c2 = cc[2];
    float wc = w[6] * c0 + w[7] * c1 + w[8] * c2;
    float best = NEGINF;
#pragma unroll
    for (int k = 0; k < KNN; k++) {
        float n0 = nb[k][0], n1 = nb[k][1], n2 = nb[k][2];
        float d = w[0] * (n0 - c0) + w[1] * (n1 - c1) + w[2] * (n2 - c2)
                + w[3] * (c1 * n2 - c2 * n1)
                + w[4] * (c2 * n0 - c0 * n2)
                + w[5] * (c0 * n1 - c1 * n0)
                + wc;
        best = fmaxf(best, d);
    }
    float sc = gg[o] * rsqrtf(vv[o] + EPSBN);
    float y = sc * best + (bb[o] - mm[o] * sc);
    cat[(size_t)p * CATC + o] = (y >= 0.f) ? y : 0.2f * y;
}

// ---------------- stacked weights: [Wa ; Wb-Wa] ----------------------------
__global__ void wuv_kernel(const float* __restrict__ W, float* __restrict__ Wuv,
                           int cout, int cin) {
    int t = blockIdx.x * blockDim.x + threadIdx.x;
    if (t >= 2 * cout * cin) return;
    int o2 = t / cin, c = t % cin;
    if (o2 < cout) Wuv[t] = W[(size_t)o2 * 2 * cin + c];
    else {
        int o = o2 - cout;
        Wuv[t] = W[(size_t)o * 2 * cin + cin + c] - W[(size_t)o * 2 * cin + c];
    }
}

// ---------------- gather-max + BN + LReLU (warp per point, float4) ----------
__global__ __launch_bounds__(256)
void gathermax2_kernel(const float* __restrict__ UV, const int* __restrict__ idx,
                       const float* __restrict__ gg, const float* __restrict__ bb,
                       const float* __restrict__ mm, const float* __restrict__ vv,
                       int cout, int off, float* __restrict__ cat) {
    __shared__ int sidx[8][KNN];
    int warp = threadIdx.x >> 5, lane = threadIdx.x & 31;
    int p = blockIdx.x * 8 + warp;       // 0..16383
    int b = p >> 12;
    if (lane < KNN) sidx[warp][lane] = idx[(size_t)p * KNN + lane];
    __syncwarp();
    int ld = 2 * cout;
    for (int c4 = lane; c4 < cout / 4; c4 += 32) {
        float4 mx = make_float4(NEGINF, NEGINF, NEGINF, NEGINF);
#pragma unroll 4
        for (int k = 0; k < KNN; k++) {
            const float4 u = *reinterpret_cast<const float4*>(
                &UV[((size_t)(b << 12) + sidx[warp][k]) * ld + 4 * c4]);
            mx.x = fmaxf(mx.x, u.x); mx.y = fmaxf(mx.y, u.y);
            mx.z = fmaxf(mx.z, u.z); mx.w = fmaxf(mx.w, u.w);
        }
        float4 vv4 = *reinterpret_cast<const float4*>(&UV[(size_t)p * ld + cout + 4 * c4]);
        float4 g4 = *reinterpret_cast<const float4*>(&gg[4 * c4]);
        float4 b4 = *reinterpret_cast<const float4*>(&bb[4 * c4]);
        float4 m4 = *reinterpret_cast<const float4*>(&mm[4 * c4]);
        float4 v4 = *reinterpret_cast<const float4*>(&vv[4 * c4]);
        float4 o;
        {
            float sc = g4.x * rsqrtf(v4.x + EPSBN);
            float y = sc * (mx.x + vv4.x) + (b4.x - m4.x * sc);
            o.x = (y >= 0.f) ? y : 0.2f * y;
        }
        {
            float sc = g4.y * rsqrtf(v4.y + EPSBN);
            float y = sc * (mx.y + vv4.y) + (b4.y - m4.y * sc);
            o.y = (y >= 0.f) ? y : 0.2f * y;
        }
        {
            float sc = g4.z * rsqrtf(v4.z + EPSBN);
            float y = sc * (mx.z + vv4.z) + (b4.z - m4.z * sc);
            o.z = (y >= 0.f) ? y : 0.2f * y;
        }
        {
            float sc = g4.w * rsqrtf(v4.w + EPSBN);
            float y = sc * (mx.w + vv4.w) + (b4.w - m4.w * sc);
            o.w = (y >= 0.f) ? y : 0.2f * y;
        }
        *reinterpret_cast<float4*>(&cat[(size_t)p * CATC + off + 4 * c4]) = o;
    }
}

// ---------------- final head: max segs + BN + LReLU + 2 linears -------------
__global__ void head_kernel(const float* __restrict__ Zp,
                            const float* __restrict__ g4, const float* __restrict__ b4,
                            const float* __restrict__ m4, const float* __restrict__ v4,
                            const float* __restrict__ We, const float* __restrict__ Wh,
                            const float* __restrict__ bh, float* __restrict__ out) {
    int b = blockIdx.x;
    int o = threadIdx.x;  // 512 threads
    __shared__ float h[512];
    __shared__ float emb[128];
    float m = NEGINF;
#pragma unroll
    for (int s = 0; s < 32; s++) m = fmaxf(m, Zp[((size_t)b * 512 + o) * 32 + s]);
    float sc = g4[o] * rsqrtf(v4[o] + EPSBN);
    float y = sc * m + (b4[o] - m4[o] * sc);
    h[o] = (y >= 0.f) ? y : 0.2f * y;
    __syncthreads();
    if (o < 128) {
        float s = 0.f;
        for (int c = 0; c < 512; c++) s += We[(size_t)o * 512 + c] * h[c];
        emb[o] = s;
    }
    __syncthreads();
    if (o < 128) {
        float s = bh[o];
        for (int c = 0; c < 128; c++) s += Wh[(size_t)o * 128 + c] * emb[c];
        out[(size_t)b * 128 + o] = s;
    }
}

// ---------------------------------------------------------------------------
extern "C" void kernel_launch(void* const* d_in, const int* in_sizes, int n_in,
                              void* d_out, int out_size) {
    const float* x = (const float*)d_in[0];
    const float *W[5], *G[5], *Bp[5], *M[5], *V[5];
    for (int l = 0; l < 5; l++) {
        W[l]  = (const float*)d_in[1 + 5 * l];
        G[l]  = (const float*)d_in[2 + 5 * l];
        Bp[l] = (const float*)d_in[3 + 5 * l];
        M[l]  = (const float*)d_in[4 + 5 * l];
        V[l]  = (const float*)d_in[5 + 5 * l];
    }
    const float* We = (const float*)d_in[26];
    const float* Wh = (const float*)d_in[27];
    const float* bh = (const float*)d_in[28];
    float* out = (float*)d_out;

    float *candV, *xxp, *cat, *UV, *Wuv, *Zp, *thr;
    int *candJ, *cnt, *idx;
    cudaGetSymbolAddress((void**)&candV, g_candV);
    cudaGetSymbolAddress((void**)&candJ, g_candJ);
    cudaGetSymbolAddress((void**)&cnt,   g_cnt);
    cudaGetSymbolAddress((void**)&thr,   g_thr);
    cudaGetSymbolAddress((void**)&idx,   g_idx);
    cudaGetSymbolAddress((void**)&xxp,   g_xx);
    cudaGetSymbolAddress((void**)&cat,   g_cat);
    cudaGetSymbolAddress((void**)&UV,    g_UV);
    cudaGetSymbolAddress((void**)&Wuv,   g_Wuv);
    cudaGetSymbolAddress((void**)&Zp,    g_Zp);

    const int M_ROWS = BATCH * NPTS;  // 16384

    int smem8   = (8   * 68 + 8   * 132) * 4 + 256;
    int smem64  = (64  * 68 + 64  * 132) * 4 + 256;
    int smem128 = (128 * 68 + 128 * 132) * 4 + 256;
    cudaFuncSetAttribute(gramcand_kernel<8, true>,
                         cudaFuncAttributeMaxDynamicSharedMemorySize, smem8);
    cudaFuncSetAttribute(gramcand_kernel<64, false>,
                         cudaFuncAttributeMaxDynamicSharedMemorySize, smem64);
    cudaFuncSetAttribute(gramcand_kernel<128, false>,
                         cudaFuncAttributeMaxDynamicSharedMemorySize, smem128);

    // side stream + events (created/destroyed every call -> identical work)
    cudaStream_t s1;
    cudaStreamCreateWithFlags(&s1, cudaStreamNonBlocking);
    cudaEvent_t eFork, eJoin;
    cudaEventCreateWithFlags(&eFork, cudaEventDisableTiming);
    cudaEventCreateWithFlags(&eJoin, cudaEventDisableTiming);

    dim3 ggrid(NPTS / 64, 1, BATCH);   // 64-row i-tiles -> 256 blocks

    // ---- block 0 (coords): gram+cand, merge, edge conv ----
    xx_kernel<<<(M_ROWS + 255) / 256, 256>>>(x, 3, 3, xxp);
    gramcand_kernel<8, true><<<ggrid, 256, smem8>>>(x, 3, xxp, candV, candJ, cnt, thr);
    merge3_kernel<<<M_ROWS / 8, 256>>>(candV, candJ, cnt, thr, idx);
    edge0_kernel<<<M_ROWS, 64>>>(x, idx, W[0], G[0], Bp[0], M[0], V[0], cat);

    // ---- blocks 1..3: gram/merge on main stream; wuv+gemm overlapped on s1 --
    struct { int cin, cout, off_in, off_out; } L[3] = {
        {64, 64, 0, 64}, {64, 128, 64, 128}, {128, 256, 128, 256}};
    for (int li = 0; li < 3; li++) {
        int l = li + 1;
        int cin = L[li].cin, cout = L[li].cout;
        const float* Xl = cat + L[li].off_in;

        xx_kernel<<<(M_ROWS + 255) / 256, 256>>>(Xl, CATC, cin, xxp);

        // fork: gemm path depends only on cat (already written)
        cudaEventRecord(eFork, 0);
        cudaStreamWaitEvent(s1, eFork, 0);
        wuv_kernel<<<(2 * cout * cin + 255) / 256, 256, 0, s1>>>(W[l], Wuv, cout, cin);
        gemm128_kernel<<<dim3(M_ROWS / 128, (2 * cout) / 128), 256, 0, s1>>>(
            Xl, CATC, Wuv, cin, 2 * cout, cin, UV, 2 * cout);
        cudaEventRecord(eJoin, s1);

        // knn path on main stream (overlaps with gemm path)
        if (cin == 64)
            gramcand_kernel<64, false><<<ggrid, 256, smem64>>>(Xl, CATC, xxp,
                                                               candV, candJ, cnt, thr);
        else
            gramcand_kernel<128, false><<<ggrid, 256, smem128>>>(Xl, CATC, xxp,
                                                                 candV, candJ, cnt, thr);
        merge3_kernel<<<M_ROWS / 8, 256>>>(candV, candJ, cnt, thr, idx);

        // join: gathermax needs both idx and UV
        cudaStreamWaitEvent(0, eJoin, 0);
        gathermax2_kernel<<<M_ROWS / 8, 256>>>(UV, idx, G[l], Bp[l], M[l], V[l],
                                               cout, L[li].off_out, cat);
    }

    // ---- layer 4 + heads ----
    conv4max128_kernel<<<dim3(4, 32, BATCH), 256>>>(cat, W[4], Zp);
    head_kernel<<<BATCH, 512>>>(Zp, G[4], Bp[4], M[4], V[4], We, Wh, bh, out);

    cudaEventDestroy(eFork);
    cudaEventDestroy(eJoin);
    cudaStreamDestroy(s1);
}

// round 17
// speedup vs baseline: 1.1374x; 1.1374x over previous
#include <cuda_runtime.h>
#include <math.h>

#define BATCH 4
#define NPTS  4096
#define KNN   20
#define CATC  512
#define EPSBN 1e-5f
#define NEGINF -3.402823466e38f
#define CAP    4096
#define SBUF   192

typedef unsigned long long u64;
typedef unsigned int u32;

// ---------------- scratch (static device globals; no allocations) ----------
__device__ float g_candV[(size_t)BATCH * NPTS * CAP];   // 256 MB
__device__ int   g_candJ[(size_t)BATCH * NPTS * CAP];   // 256 MB
__device__ int   g_cnt  [BATCH * NPTS];
__device__ float g_thr  [BATCH * NPTS];
__device__ int   g_idx [(size_t)BATCH * NPTS * KNN];
__device__ float g_xx  [BATCH * NPTS];
__device__ float g_cat [(size_t)BATCH * NPTS * CATC];   // 32 MB
__device__ float g_UV  [(size_t)BATCH * NPTS * 512];    // 32 MB
__device__ float g_Wuv [512 * 256];
__device__ float g_Zp  [BATCH * 512 * 32];

// ===================== packed f32x2 helpers =================================
__device__ __forceinline__ void fma2(u64& d, u64 a, u64 b) {
    asm("fma.rn.f32x2 %0, %1, %2, %0;" : "+l"(d) : "l"(a), "l"(b));
}
__device__ __forceinline__ u64 dup2(float a) {
    u64 d;
    asm("mov.b64 %0, {%1, %1};" : "=l"(d) : "f"(a));
    return d;
}
__device__ __forceinline__ void unpack2(u64 p, float& lo, float& hi) {
    asm("mov.b64 {%0, %1}, %2;" : "=f"(lo), "=f"(hi) : "l"(p));
}

// monotonic float->u32 order map
__device__ __forceinline__ u32 mapf(float f) {
    u32 u = __float_as_uint(f);
    return u ^ ((u32)(((int)u) >> 31) | 0x80000000u);
}

// ---------------- row squared norms (coords only) ---------------------------
__global__ void xx_kernel(const float* __restrict__ X, float* __restrict__ xx) {
    int r = blockIdx.x * blockDim.x + threadIdx.x;
    if (r >= BATCH * NPTS) return;
    const float* row = X + (size_t)r * 3;
    float a = row[0], b = row[1], c = row[2];
    xx[r] = a * a + b * b + c * c;
}

// ===================== fused Gram + running-top2 candidate emit =============
// (exact R11/R15 body — best measured; gram register budget untouched)
template <int C, bool COORD>
__global__ __launch_bounds__(256, 1)
void gramcand_kernel(const float* __restrict__ X, int ldx,
                     const float* __restrict__ xx,
                     float* __restrict__ candV, int* __restrict__ candJ,
                     int* __restrict__ cnt, float* __restrict__ thr) {
    extern __shared__ float smem[];
    float* As = smem;
    float* Bs = smem + C * 132;
    int* scnt = (int*)(Bs + C * 132);
#define AS_(k, r) As[(k) * 132 + (r)]
#define BS_(k, r) Bs[(k) * 132 + (r)]

    int b = blockIdx.z;
    const float* Xb  = X  + (size_t)b * NPTS * ldx;
    const float* xxb = xx + (size_t)b * NPTS;
    int i0 = blockIdx.x * 128;
    int tid = threadIdx.x, tx = tid & 15, ty = tid >> 4;
    int lr = tid >> 1, lh = tid & 1;
    int gi0 = b * NPTS + i0;

    if (COORD) {
        if (tid < 128) {
            const float* xr = &Xb[(size_t)(i0 + tid) * 3];
            AS_(0, tid) = xr[0]; AS_(1, tid) = xr[1]; AS_(2, tid) = xr[2];
#pragma unroll
            for (int k = 3; k < C; k++) AS_(k, tid) = 0.f;
        }
    } else {
#pragma unroll
        for (int m = 0; m < C / 8; m++) {
            float4 v = *reinterpret_cast<const float4*>(
                &Xb[(size_t)(i0 + lr) * ldx + m * 8 + lh * 4]);
            AS_(m * 8 + lh * 4 + 0, lr) = v.x;
            AS_(m * 8 + lh * 4 + 1, lr) = v.y;
            AS_(m * 8 + lh * 4 + 2, lr) = v.z;
            AS_(m * 8 + lh * 4 + 3, lr) = v.w;
        }
    }
    if (tid < 128) scnt[tid] = 0;

    float l1[8], l2[8];
#pragma unroll
    for (int rr = 0; rr < 8; rr++) { l1[rr] = NEGINF; l2[rr] = NEGINF; }

    __syncthreads();

    for (int jt = 0; jt < 32; jt++) {
        int j0 = jt * 128;
        if (COORD) {
            if (tid < 128) {
                const float* xr = &Xb[(size_t)(j0 + tid) * 3];
                BS_(0, tid) = xr[0]; BS_(1, tid) = xr[1]; BS_(2, tid) = xr[2];
#pragma unroll
                for (int k = 3; k < C; k++) BS_(k, tid) = 0.f;
            }
        } else {
#pragma unroll
            for (int m = 0; m < C / 8; m++) {
                float4 v = *reinterpret_cast<const float4*>(
                    &Xb[(size_t)(j0 + lr) * ldx + m * 8 + lh * 4]);
                BS_(m * 8 + lh * 4 + 0, lr) = v.x;
                BS_(m * 8 + lh * 4 + 1, lr) = v.y;
                BS_(m * 8 + lh * 4 + 2, lr) = v.z;
                BS_(m * 8 + lh * 4 + 3, lr) = v.w;
            }
        }
        __syncthreads();

        u64 acc[8][4];
#pragma unroll
        for (int ii = 0; ii < 8; ii++)
#pragma unroll
            for (int jp = 0; jp < 4; jp++) acc[ii][jp] = 0ULL;

        for (int kk0 = 0; kk0 < C; kk0 += 8) {
#pragma unroll
            for (int k2 = 0; k2 < 8; k2++) {
                int kk = kk0 + k2;
                float4 a0 = *reinterpret_cast<const float4*>(&AS_(kk, ty * 8));
                float4 a1 = *reinterpret_cast<const float4*>(&AS_(kk, ty * 8 + 4));
                ulonglong2 b0 = *reinterpret_cast<const ulonglong2*>(&BS_(kk, tx * 4));
                ulonglong2 b1 = *reinterpret_cast<const ulonglong2*>(&BS_(kk, 64 + tx * 4));
                u64 bq[4] = {b0.x, b0.y, b1.x, b1.y};
                float a[8] = {a0.x, a0.y, a0.z, a0.w, a1.x, a1.y, a1.z, a1.w};
#pragma unroll
                for (int ii = 0; ii < 8; ii++) {
                    u64 ad = dup2(a[ii]);
#pragma unroll
                    for (int jp = 0; jp < 4; jp++) fma2(acc[ii][jp], ad, bq[jp]);
                }
            }
        }

        float4 xjA = *reinterpret_cast<const float4*>(&xxb[j0 + tx * 4]);
        float4 xjB = *reinterpret_cast<const float4*>(&xxb[j0 + 64 + tx * 4]);
        float xj[8] = {xjA.x, xjA.y, xjA.z, xjA.w, xjB.x, xjB.y, xjB.z, xjB.w};

#pragma unroll
        for (int rr = 0; rr < 8; rr++) {
            float c[8];
#pragma unroll
            for (int jp = 0; jp < 4; jp++) unpack2(acc[rr][jp], c[jp * 2], c[jp * 2 + 1]);
            float dv[8];
#pragma unroll
            for (int jj = 0; jj < 8; jj++) dv[jj] = 2.f * c[jj] - xj[jj];

            float m1 = l1[rr], m2 = l2[rr];
#pragma unroll
            for (int jj = 0; jj < 8; jj++) {
                float v = dv[jj];
                float n1 = fmaxf(m1, v);
                m2 = fmaxf(m2, fminf(m1, v));
                m1 = n1;
            }
            l1[rr] = m1; l2[rr] = m2;

            float t = m2;
#pragma unroll
            for (int off = 1; off < 16; off <<= 1)
                t = fminf(t, __shfl_xor_sync(0xffffffffu, t, off));

            int rloc = ty * 8 + rr;
            size_t base = (size_t)(gi0 + rloc) * CAP;
#pragma unroll
            for (int jj = 0; jj < 8; jj++) {
                if (dv[jj] >= t) {
                    int pos = atomicAdd(&scnt[rloc], 1);   // pos < NPTS = CAP always
                    int j = (jj < 4) ? (j0 + tx * 4 + jj) : (j0 + 64 + tx * 4 + jj - 4);
                    candV[base + pos] = dv[jj];
                    candJ[base + pos] = j;
                }
            }
        }
        __syncthreads();
    }

    if (tid < 128) cnt[gi0 + tid] = scnt[tid];
#pragma unroll
    for (int rr = 0; rr < 8; rr++) {
        float t = l2[rr];
#pragma unroll
        for (int off = 1; off < 16; off <<= 1)
            t = fminf(t, __shfl_xor_sync(0xffffffffu, t, off));
        if (tx == 0) thr[gi0 + ty * 8 + rr] = t;
    }
#undef AS_
#undef BS_
}

// ---------------- merge candidates -> exact top-K (single-pass) ------------
__global__ __launch_bounds__(256)
void merge3_kernel(const float* __restrict__ candV, const int* __restrict__ candJ,
                   const int* __restrict__ cnt, const float* __restrict__ thr,
                   int* __restrict__ idx) {
    __shared__ u64 surv[8][SBUF];
    int warp = threadIdx.x >> 5, lane = threadIdx.x & 31;
    int row = blockIdx.x * 8 + warp;
    int n = cnt[row];
    float T = thr[row];
    const float* cv = candV + (size_t)row * CAP;
    const int*   cj = candJ + (size_t)row * CAP;

    int sc = 0;
    for (int base = 0; base < n; base += 32) {
        int t = base + lane;
        float v = (t < n) ? cv[t] : NEGINF;
        bool keep = (t < n) && (v >= T);
        unsigned mk = __ballot_sync(0xffffffffu, keep);
        if (keep) {
            int pos = sc + __popc(mk & ((1u << lane) - 1u));
            if (pos < SBUF)
                surv[warp][pos] = ((u64)mapf(v) << 32) | (u32)(4095 - cj[t]);
        }
        sc += __popc(mk);
    }
    __syncwarp();

    int* outp = idx + (size_t)row * KNN;
    if (sc <= SBUF) {
        for (int k = 0; k < KNN; k++) {
            u64 best = 0ULL; int bpos = -1;
            for (int t = lane; t < sc; t += 32) {
                u64 kv = surv[warp][t];
                if (kv > best) { best = kv; bpos = t; }
            }
#pragma unroll
            for (int off = 16; off > 0; off >>= 1) {
                u64 ov = __shfl_xor_sync(0xffffffffu, best, off);
                int op = __shfl_xor_sync(0xffffffffu, bpos, off);
                if (ov > best) { best = ov; bpos = op; }
            }
            if (lane == 0) {
                outp[k] = 4095 - (int)(best & 0xFFFu);
                surv[warp][bpos] = 0ULL;
            }
            __syncwarp();
        }
    } else {
        u64 last = 0xFFFFFFFFFFFFFFFFULL;
        for (int k = 0; k < KNN; k++) {
            u64 best = 0ULL;
            for (int t = lane; t < n; t += 32) {
                u64 kv = ((u64)mapf(cv[t]) << 32) | (u32)(4095 - cj[t]);
                if (kv < last && kv > best) best = kv;
            }
#pragma unroll
            for (int off = 16; off > 0; off >>= 1) {
                u64 ov = __shfl_xor_sync(0xffffffffu, best, off);
                if (ov > best) best = ov;
            }
            if (lane == 0) outp[k] = 4095 - (int)(best & 0xFFFu);
            last = best;
        }
    }
}

// ---------------- generic NT GEMM: Out[i,j] = A[i,:]·B[j,:] -----------------
#define GPADF 132
__global__ __launch_bounds__(256, 2)
void gemm128_kernel(const float* __restrict__ A, int lda,
                    const float* __restrict__ B, int ldb, int nB,
                    int K, float* __restrict__ Out, int ldo) {
    __shared__ float As[8][GPADF];
    __shared__ float Bs[8][GPADF];
    int i0 = blockIdx.x * 128, j0 = blockIdx.y * 128;
    int tid = threadIdx.x, tx = tid & 15, ty = tid >> 4;
    int lr = tid >> 1, lh = tid & 1;

    u64 acc[8][4];
#pragma unroll
    for (int ii = 0; ii < 8; ii++)
#pragma unroll
        for (int jp = 0; jp < 4; jp++) acc[ii][jp] = 0ULL;

    int nt = K >> 3;
    float4 pa = *reinterpret_cast<const float4*>(&A[(size_t)(i0 + lr) * lda + lh * 4]);
    float4 pb = (j0 + lr < nB)
              ? *reinterpret_cast<const float4*>(&B[(size_t)(j0 + lr) * ldb + lh * 4])
              : make_float4(0.f, 0.f, 0.f, 0.f);

    for (int kt = 0; kt < nt; kt++) {
        As[lh * 4 + 0][lr] = pa.x; As[lh * 4 + 1][lr] = pa.y;
        As[lh * 4 + 2][lr] = pa.z; As[lh * 4 + 3][lr] = pa.w;
        Bs[lh * 4 + 0][lr] = pb.x; Bs[lh * 4 + 1][lr] = pb.y;
        Bs[lh * 4 + 2][lr] = pb.z; Bs[lh * 4 + 3][lr] = pb.w;
        __syncthreads();
        if (kt + 1 < nt) {
            int k0 = (kt + 1) * 8 + lh * 4;
            pa = *reinterpret_cast<const float4*>(&A[(size_t)(i0 + lr) * lda + k0]);
            pb = (j0 + lr < nB)
               ? *reinterpret_cast<const float4*>(&B[(size_t)(j0 + lr) * ldb + k0])
               : make_float4(0.f, 0.f, 0.f, 0.f);
        }
#pragma unroll
        for (int kk = 0; kk < 8; kk++) {
            float4 a0 = *reinterpret_cast<const float4*>(&As[kk][ty * 8]);
            float4 a1 = *reinterpret_cast<const float4*>(&As[kk][ty * 8 + 4]);
            ulonglong2 b0 = *reinterpret_cast<const ulonglong2*>(&Bs[kk][tx * 8]);
            ulonglong2 b1 = *reinterpret_cast<const ulonglong2*>(&Bs[kk][tx * 8 + 4]);
            u64 bq[4] = {b0.x, b0.y, b1.x, b1.y};
            float a[8] = {a0.x, a0.y, a0.z, a0.w, a1.x, a1.y, a1.z, a1.w};
#pragma unroll
            for (int ii = 0; ii < 8; ii++) {
                u64 ad = dup2(a[ii]);
#pragma unroll
                for (int jp = 0; jp < 4; jp++) fma2(acc[ii][jp], ad, bq[jp]);
            }
        }
        __syncthreads();
    }

    int j = j0 + tx * 8;
    if (j < nB) {
#pragma unroll
        for (int ii = 0; ii < 8; ii++) {
            int i = i0 + ty * 8 + ii;
            float c[8];
#pragma unroll
            for (int jp = 0; jp < 4; jp++) unpack2(acc[ii][jp], c[jp * 2], c[jp * 2 + 1]);
            float* dst = &Out[(size_t)i * ldo + j];
            *reinterpret_cast<float4*>(dst)     = make_float4(c[0], c[1], c[2], c[3]);
            *reinterpret_cast<float4*>(dst + 4) = make_float4(c[4], c[5], c[6], c[7]);
        }
    }
}

// ---------------- layer 4: GEMM + max-over-N epilogue -----------------------
__global__ __launch_bounds__(256, 2)
void conv4max128_kernel(const float* __restrict__ cat, const float* __restrict__ W4,
                        float* __restrict__ Zp) {
    __shared__ float As[8][GPADF];
    __shared__ float Bs[8][GPADF];
    __shared__ float red[128][17];
    int b = blockIdx.z, seg = blockIdx.y;
    int o0 = blockIdx.x * 128, n0 = seg * 128;
    const float* catb = cat + (size_t)b * NPTS * CATC;
    int tid = threadIdx.x, tx = tid & 15, ty = tid >> 4;
    int lr = tid >> 1, lh = tid & 1;

    u64 acc[8][4];
#pragma unroll
    for (int ii = 0; ii < 8; ii++)
#pragma unroll
        for (int jp = 0; jp < 4; jp++) acc[ii][jp] = 0ULL;

    float4 pa = *reinterpret_cast<const float4*>(&W4  [(size_t)(o0 + lr) * CATC + lh * 4]);
    float4 pb = *reinterpret_cast<const float4*>(&catb[(size_t)(n0 + lr) * CATC + lh * 4]);

    for (int kt = 0; kt < 64; kt++) {
        As[lh * 4 + 0][lr] = pa.x; As[lh * 4 + 1][lr] = pa.y;
        As[lh * 4 + 2][lr] = pa.z; As[lh * 4 + 3][lr] = pa.w;
        Bs[lh * 4 + 0][lr] = pb.x; Bs[lh * 4 + 1][lr] = pb.y;
        Bs[lh * 4 + 2][lr] = pb.z; Bs[lh * 4 + 3][lr] = pb.w;
        __syncthreads();
        if (kt + 1 < 64) {
            int k0 = (kt + 1) * 8 + lh * 4;
            pa = *reinterpret_cast<const float4*>(&W4  [(size_t)(o0 + lr) * CATC + k0]);
            pb = *reinterpret_cast<const float4*>(&catb[(size_t)(n0 + lr) * CATC + k0]);
        }
#pragma unroll
        for (int kk = 0; kk < 8; kk++) {
            float4 a0 = *reinterpret_cast<const float4*>(&As[kk][ty * 8]);
            float4 a1 = *reinterpret_cast<const float4*>(&As[kk][ty * 8 + 4]);
            ulonglong2 b0 = *reinterpret_cast<const ulonglong2*>(&Bs[kk][tx * 8]);
            ulonglong2 b1 = *reinterpret_cast<const ulonglong2*>(&Bs[kk][tx * 8 + 4]);
            u64 bq[4] = {b0.x, b0.y, b1.x, b1.y};
            float a[8] = {a0.x, a0.y, a0.z, a0.w, a1.x, a1.y, a1.z, a1.w};
#pragma unroll
            for (int ii = 0; ii < 8; ii++) {
                u64 ad = dup2(a[ii]);
#pragma unroll
                for (int jp = 0; jp < 4; jp++) fma2(acc[ii][jp], ad, bq[jp]);
            }
        }
        __syncthreads();
    }

#pragma unroll
    for (int ii = 0; ii < 8; ii++) {
        float c[8];
#pragma unroll
        for (int jp = 0; jp < 4; jp++) unpack2(acc[ii][jp], c[jp * 2], c[jp * 2 + 1]);
        float m = c[0];
#pragma unroll
        for (int q = 1; q < 8; q++) m = fmaxf(m, c[q]);
        red[ty * 8 + ii][tx] = m;
    }
    __syncthreads();
    if (tid < 128) {
        float m = red[tid][0];
#pragma unroll
        for (int t = 1; t < 16; t++) m = fmaxf(m, red[tid][t]);
        Zp[((size_t)b * 512 + o0 + tid) * 32 + seg] = m;
    }
}

// ---------------- block 0 conv + fused xx of its output --------------------
__global__ void edge0_kernel(const float* __restrict__ x, const int* __restrict__ idx,
                             const float* __restrict__ W,  const float* __restrict__ gg,
                             const float* __restrict__ bb, const float* __restrict__ mm,
                             const float* __restrict__ vv, float* __restrict__ cat,
                             float* __restrict__ xxp) {
    int p = blockIdx.x;
    int b = p / NPTS;
    __shared__ float nb[KNN][3];
    __shared__ float Ws[64 * 9];
    __shared__ float cc[3];
    __shared__ float sq[64];
    int tid = threadIdx.x;  // 64 threads
    if (tid < 3) cc[tid] = x[(size_t)p * 3 + tid];
    if (tid < KNN) {
        int j = idx[(size_t)p * KNN + tid];
        const float* xr = x + ((size_t)b * NPTS + j) * 3;
        nb[tid][0] = xr[0]; nb[tid][1] = xr[1]; nb[tid][2] = xr[2];
    }
    for (int t = tid; t < 576; t += 64) Ws[t] = W[t];
    __syncthreads();

    int o = tid;
    const float* w = &Ws[o * 9];
    float c0 = cc[0], c1 = cc[1], c2 = cc[2];
    float wc = w[6] * c0 + w[7] * c1 + w[8] * c2;
    float best = NEGINF;
#pragma unroll
    for (int k = 0; k < KNN; k++) {
        float n0 = nb[k][0], n1 = nb[k][1], n2 = nb[k][2];
        float d = w[0] * (n0 - c0) + w[1] * (n1 - c1) + w[2] * (n2 - c2)
                + w[3] * (c1 * n2 - c2 * n1)
                + w[4] * (c2 * n0 - c0 * n2)
                + w[5] * (c0 * n1 - c1 * n0)
                + wc;
        best = fmaxf(best, d);
    }
    float sc = gg[o] * rsqrtf(vv[o] + EPSBN);
    float y = sc * best + (bb[o] - mm[o] * sc);
    float val = (y >= 0.f) ? y : 0.2f * y;
    cat[(size_t)p * CATC + o] = val;

    // fused xx for next layer's gram (input = these 64 channels)
    sq[tid] = val * val;
    __syncthreads();
#pragma unroll
    for (int st = 32; st > 0; st >>= 1) {
        if (tid < st) sq[tid] += sq[tid + st];
        __syncthreads();
    }
    if (tid == 0) xxp[p] = sq[0];
}

// ---------------- stacked weights: [Wa ; Wb-Wa] ----------------------------
__global__ void wuv_kernel(const float* __restrict__ W, float* __restrict__ Wuv,
                           int cout, int cin) {
    int t = blockIdx.x * blockDim.x + threadIdx.x;
    if (t >= 2 * cout * cin) return;
    int o2 = t / cin, c = t % cin;
    if (o2 < cout) Wuv[t] = W[(size_t)o2 * 2 * cin + c];
    else {
        int o = o2 - cout;
        Wuv[t] = W[(size_t)o * 2 * cin + cin + c] - W[(size_t)o * 2 * cin + c];
    }
}

// ---------------- gather-max + BN + LReLU + fused xx of output --------------
__global__ __launch_bounds__(256)
void gathermax2_kernel(const float* __restrict__ UV, const int* __restrict__ idx,
                       const float* __restrict__ gg, const float* __restrict__ bb,
                       const float* __restrict__ mm, const float* __restrict__ vv,
                       int cout, int off, float* __restrict__ cat,
                       float* __restrict__ xxp) {
    __shared__ int sidx[8][KNN];
    int warp = threadIdx.x >> 5, lane = threadIdx.x & 31;
    int p = blockIdx.x * 8 + warp;       // 0..16383
    int b = p >> 12;
    if (lane < KNN) sidx[warp][lane] = idx[(size_t)p * KNN + lane];
    __syncwarp();
    int ld = 2 * cout;
    float accxx = 0.f;
    for (int c4 = lane; c4 < cout / 4; c4 += 32) {
        float4 mx = make_float4(NEGINF, NEGINF, NEGINF, NEGINF);
#pragma unroll 4
        for (int k = 0; k < KNN; k++) {
            const float4 u = *reinterpret_cast<const float4*>(
                &UV[((size_t)(b << 12) + sidx[warp][k]) * ld + 4 * c4]);
            mx.x = fmaxf(mx.x, u.x); mx.y = fmaxf(mx.y, u.y);
            mx.z = fmaxf(mx.z, u.z); mx.w = fmaxf(mx.w, u.w);
        }
        float4 vv4 = *reinterpret_cast<const float4*>(&UV[(size_t)p * ld + cout + 4 * c4]);
        float4 g4 = *reinterpret_cast<const float4*>(&gg[4 * c4]);
        float4 b4 = *reinterpret_cast<const float4*>(&bb[4 * c4]);
        float4 m4 = *reinterpret_cast<const float4*>(&mm[4 * c4]);
        float4 v4 = *reinterpret_cast<const float4*>(&vv[4 * c4]);
        float4 o;
        {
            float sc = g4.x * rsqrtf(v4.x + EPSBN);
            float y = sc * (mx.x + vv4.x) + (b4.x - m4.x * sc);
            o.x = (y >= 0.f) ? y : 0.2f * y;
        }
        {
            float sc = g4.y * rsqrtf(v4.y + EPSBN);
            float y = sc * (mx.y + vv4.y) + (b4.y - m4.y * sc);
            o.y = (y >= 0.f) ? y : 0.2f * y;
        }
        {
            float sc = g4.z * rsqrtf(v4.z + EPSBN);
            float y = sc * (mx.z + vv4.z) + (b4.z - m4.z * sc);
            o.z = (y >= 0.f) ? y : 0.2f * y;
        }
        {
            float sc = g4.w * rsqrtf(v4.w + EPSBN);
            float y = sc * (mx.w + vv4.w) + (b4.w - m4.w * sc);
            o.w = (y >= 0.f) ? y : 0.2f * y;
        }
        accxx += o.x * o.x + o.y * o.y + o.z * o.z + o.w * o.w;
        *reinterpret_cast<float4*>(&cat[(size_t)p * CATC + off + 4 * c4]) = o;
    }
    // fused xx for next layer's gram (input = channels just written)
#pragma unroll
    for (int offd = 16; offd > 0; offd >>= 1)
        accxx += __shfl_xor_sync(0xffffffffu, accxx, offd);
    if (lane == 0) xxp[p] = accxx;
}

// ---------------- final head: max segs + BN + LReLU + 2 linears -------------
__global__ void head_kernel(const float* __restrict__ Zp,
                            const float* __restrict__ g4, const float* __restrict__ b4,
                            const float* __restrict__ m4, const float* __restrict__ v4,
                            const float* __restrict__ We, const float* __restrict__ Wh,
                            const float* __restrict__ bh, float* __restrict__ out) {
    int b = blockIdx.x;
    int o = threadIdx.x;  // 512 threads
    __shared__ float h[512];
    __shared__ float emb[128];
    float m = NEGINF;
#pragma unroll
    for (int s = 0; s < 32; s++) m = fmaxf(m, Zp[((size_t)b * 512 + o) * 32 + s]);
    float sc = g4[o] * rsqrtf(v4[o] + EPSBN);
    float y = sc * m + (b4[o] - m4[o] * sc);
    h[o] = (y >= 0.f) ? y : 0.2f * y;
    __syncthreads();
    if (o < 128) {
        float s = 0.f;
        for (int c = 0; c < 512; c++) s += We[(size_t)o * 512 + c] * h[c];
        emb[o] = s;
    }
    __syncthreads();
    if (o < 128) {
        float s = bh[o];
        for (int c = 0; c < 128; c++) s += Wh[(size_t)o * 128 + c] * emb[c];
        out[(size_t)b * 128 + o] = s;
    }
}

// ---------------------------------------------------------------------------
extern "C" void kernel_launch(void* const* d_in, const int* in_sizes, int n_in,
                              void* d_out, int out_size) {
    const float* x = (const float*)d_in[0];
    const float *W[5], *G[5], *Bp[5], *M[5], *V[5];
    for (int l = 0; l < 5; l++) {
        W[l]  = (const float*)d_in[1 + 5 * l];
        G[l]  = (const float*)d_in[2 + 5 * l];
        Bp[l] = (const float*)d_in[3 + 5 * l];
        M[l]  = (const float*)d_in[4 + 5 * l];
        V[l]  = (const float*)d_in[5 + 5 * l];
    }
    const float* We = (const float*)d_in[26];
    const float* Wh = (const float*)d_in[27];
    const float* bh = (const float*)d_in[28];
    float* out = (float*)d_out;

    float *candV, *xxp, *cat, *UV, *Wuv, *Zp, *thr;
    int *candJ, *cnt, *idx;
    cudaGetSymbolAddress((void**)&candV, g_candV);
    cudaGetSymbolAddress((void**)&candJ, g_candJ);
    cudaGetSymbolAddress((void**)&cnt,   g_cnt);
    cudaGetSymbolAddress((void**)&thr,   g_thr);
    cudaGetSymbolAddress((void**)&idx,   g_idx);
    cudaGetSymbolAddress((void**)&xxp,   g_xx);
    cudaGetSymbolAddress((void**)&cat,   g_cat);
    cudaGetSymbolAddress((void**)&UV,    g_UV);
    cudaGetSymbolAddress((void**)&Wuv,   g_Wuv);
    cudaGetSymbolAddress((void**)&Zp,    g_Zp);

    const int M_ROWS = BATCH * NPTS;  // 16384

    int smem8   = (2 * 8   * 132) * 4 + 512;
    int smem64  = (2 * 64  * 132) * 4 + 512;
    int smem128 = (2 * 128 * 132) * 4 + 512;
    cudaFuncSetAttribute(gramcand_kernel<8, true>,
                         cudaFuncAttributeMaxDynamicSharedMemorySize, smem8);
    cudaFuncSetAttribute(gramcand_kernel<64, false>,
                         cudaFuncAttributeMaxDynamicSharedMemorySize, smem64);
    cudaFuncSetAttribute(gramcand_kernel<128, false>,
                         cudaFuncAttributeMaxDynamicSharedMemorySize, smem128);

    // side stream + events (created/destroyed every call -> identical work)
    cudaStream_t s1;
    cudaStreamCreateWithFlags(&s1, cudaStreamNonBlocking);
    cudaEvent_t eFork, eJoin;
    cudaEventCreateWithFlags(&eFork, cudaEventDisableTiming);
    cudaEventCreateWithFlags(&eJoin, cudaEventDisableTiming);

    dim3 ggrid(NPTS / 128, 1, BATCH);

    // ---- block 0 (coords): xx, gram+cand, merge, edge conv (writes xx) ----
    xx_kernel<<<(M_ROWS + 255) / 256, 256>>>(x, xxp);
    gramcand_kernel<8, true><<<ggrid, 256, smem8>>>(x, 3, xxp, candV, candJ, cnt, thr);
    merge3_kernel<<<M_ROWS / 8, 256>>>(candV, candJ, cnt, thr, idx);
    edge0_kernel<<<M_ROWS, 64>>>(x, idx, W[0], G[0], Bp[0], M[0], V[0], cat, xxp);

    // ---- blocks 1..3: gram/merge on main; wuv+gemm overlapped on s1 --------
    // xx for each layer comes fused from the previous layer's producer.
    struct { int cin, cout, off_in, off_out; } L[3] = {
        {64, 64, 0, 64}, {64, 128, 64, 128}, {128, 256, 128, 256}};
    for (int li = 0; li < 3; li++) {
        int l = li + 1;
        int cin = L[li].cin, cout = L[li].cout;
        const float* Xl = cat + L[li].off_in;

        // fork: gemm path depends only on cat (already written)
        cudaEventRecord(eFork, 0);
        cudaStreamWaitEvent(s1, eFork, 0);
        wuv_kernel<<<(2 * cout * cin + 255) / 256, 256, 0, s1>>>(W[l], Wuv, cout, cin);
        gemm128_kernel<<<dim3(M_ROWS / 128, (2 * cout) / 128), 256, 0, s1>>>(
            Xl, CATC, Wuv, cin, 2 * cout, cin, UV, 2 * cout);
        cudaEventRecord(eJoin, s1);

        // knn path on main stream (overlaps with gemm path)
        if (cin == 64)
            gramcand_kernel<64, false><<<ggrid, 256, smem64>>>(Xl, CATC, xxp,
                                                               candV, candJ, cnt, thr);
        else
            gramcand_kernel<128, false><<<ggrid, 256, smem128>>>(Xl, CATC, xxp,
                                                                 candV, candJ, cnt, thr);
        merge3_kernel<<<M_ROWS / 8, 256>>>(candV, candJ, cnt, thr, idx);

        // join: gathermax needs both idx and UV; writes cat + next xx
        cudaStreamWaitEvent(0, eJoin, 0);
        gathermax2_kernel<<<M_ROWS / 8, 256>>>(UV, idx, G[l], Bp[l], M[l], V[l],
                                               cout, L[li].off_out, cat, xxp);
    }

    // ---- layer 4 + heads ----
    conv4max128_kernel<<<dim3(4, 32, BATCH), 256>>>(cat, W[4], Zp);
    head_kernel<<<BATCH, 512>>>(Zp, G[4], Bp[4], M[4], V[4], We, Wh, bh, out);

    cudaEventDestroy(eFork);
    cudaEventDestroy(eJoin);
    cudaStreamDestroy(s1);
}